// round 17
// baseline (speedup 1.0000x reference)
#include <cuda_runtime.h>
#include <cuda_bf16.h>
#include <cstdint>

// VectorQuantizer forward (GB300, mma.sync bf16 HMMA):
//   out  = x  (reference returns the rearranged input == x bit-exactly)
//   loss = 1.25/(N*E) * ( sum(x^2) + sum_n min_k( ||e_k||^2 - 2 x_n . e_k ) )
// N=32768, E=256, K=1024.  x: [32,256,32,32] (vector n=(b,hw), dim stride 1024).
// Mainloop uses a 4-deep cp.async ring of 8KB B tiles with the issue stream
// interleaved into the MMA stream (LSU/tensor overlap instead of alternation).

#define NVEC  32768
#define EDIM  256
#define KCODE 1024

#define CTA_M 128
#define CTA_N 128             // codes per chunk
#define NCH   (KCODE/CTA_N)   // 8
#define TPC   8               // B tiles per chunk (32 dims each)
#define NT    (NCH*TPC)       // 64 B tiles

#define BROW  80              // 64B of bf16 dims + 16B pad (conflict-free ldsm)
#define BSLOT (128*BROW)      // 10240 bytes per ring slot

// smem layout (bytes).  A: 128 rows x 512B bf16, XOR-swizzled.
#define SM_A   0              // 65536
#define SM_BR  65536          // 4 x 10240 ring = 40960
#define SM_XS  (SM_BR + 2*BSLOT)  // phase-1 f32 stage (16KB) overlays slots 2,3
#define SM_EN  106496         // 4096
#define SM_RM  110592         // 2048
#define SMEM_TOTAL 112640     // x2 CTAs = 225280 <= 228KB/SM

__device__ double g_sumx2;
__device__ double g_summin;
__device__ unsigned g_count;
__device__ float  g_enorm2[KCODE];
__device__ __nv_bfloat16 g_cbb[(size_t)KCODE * EDIM];

// ---------------- PTX helpers ----------------
__device__ __forceinline__ uint32_t smem_u32(const void* p) {
    uint32_t a;
    asm("{ .reg .u64 t; cvta.to.shared.u64 t, %1; cvt.u32.u64 %0, t; }"
        : "=r"(a) : "l"(p));
    return a;
}
__device__ __forceinline__ uint32_t pack_bf16x2(float lo, float hi) {
    uint32_t r;
    asm("cvt.rn.bf16x2.f32 %0, %1, %2;" : "=r"(r) : "f"(hi), "f"(lo));
    return r;
}
__device__ __forceinline__ void ldsm_x4(uint32_t* r, uint32_t addr) {
    asm volatile("ldmatrix.sync.aligned.m8n8.x4.shared.b16 {%0,%1,%2,%3}, [%4];"
                 : "=r"(r[0]), "=r"(r[1]), "=r"(r[2]), "=r"(r[3]) : "r"(addr));
}
__device__ __forceinline__ void ldsm_x4t(uint32_t* r, uint32_t addr) {
    asm volatile("ldmatrix.sync.aligned.m8n8.x4.trans.shared.b16 {%0,%1,%2,%3}, [%4];"
                 : "=r"(r[0]), "=r"(r[1]), "=r"(r[2]), "=r"(r[3]) : "r"(addr));
}
__device__ __forceinline__ void mma16816(float* d, const uint32_t* a, const uint32_t* b) {
    asm volatile(
        "mma.sync.aligned.m16n8k16.row.col.f32.bf16.bf16.f32 "
        "{%0,%1,%2,%3}, {%4,%5,%6,%7}, {%8,%9}, {%0,%1,%2,%3};"
        : "+f"(d[0]), "+f"(d[1]), "+f"(d[2]), "+f"(d[3])
        : "r"(a[0]), "r"(a[1]), "r"(a[2]), "r"(a[3]), "r"(b[0]), "r"(b[1]));
}
#define CP_ASYNC16(s, g) \
    asm volatile("cp.async.cg.shared.global [%0], [%1], 16;" :: "r"(s), "l"(g))
#define CP_COMMIT() asm volatile("cp.async.commit_group;" ::: "memory")
#define CP_WAIT2()  asm volatile("cp.async.wait_group 2;" ::: "memory")

// ---------------- prep: init + codebook bf16 + ||e||^2 ----------------
__global__ void prep_kernel(const float* __restrict__ cb) {
    int tid = threadIdx.x;                           // 256 blocks x 256 threads
    int j = blockIdx.x * 256 + tid;                  // float4 index, 0..65535
    if (j == 0) { g_sumx2 = 0.0; g_summin = 0.0; g_count = 0u; }
    float4 v = ((const float4*)cb)[j];
    uint2 p;
    p.x = pack_bf16x2(v.x, v.y);
    p.y = pack_bf16x2(v.z, v.w);
    ((uint2*)g_cbb)[j] = p;
    float s = v.x * v.x + v.y * v.y + v.z * v.z + v.w * v.w;
#pragma unroll
    for (int o = 16; o; o >>= 1) s += __shfl_xor_sync(0xffffffffu, s, o);
    __shared__ float aa[8];
    if ((tid & 31) == 0) aa[tid >> 5] = s;
    __syncthreads();
    if ((tid & 63) == 0) {
        int g = tid >> 6;                            // 4 codes per block
        g_enorm2[blockIdx.x * 4 + g] = aa[2 * g] + aa[2 * g + 1];
    }
}

// ---------------- fused GEMM + row-min + sum(x^2) + out-copy + loss ----------------
extern __shared__ __align__(1024) unsigned char smem[];

// B tile t: chunk nc=t>>3, k-slice t&7 (32 dims = 64B per code row), padded
// to BROW=80B rows (bank-conflict-free ldsm without XOR).  512 x 16B ops per
// tile; half h issues 256 of them (1 op/thread).
__device__ __forceinline__ void issueB_half(uint32_t sb, int tid, int t, int h) {
    uint32_t dstb = sb + SM_BR + (uint32_t)(t & 3) * BSLOT;
    const char* gp = (const char*)g_cbb + (size_t)(t >> 3) * (128 * 512)
                   + (size_t)(t & 7) * 64;
    int i = tid + h * 256;                           // 0..511
    int r = i >> 2;
    uint32_t c = (uint32_t)(i & 3) * 16;
    CP_ASYNC16(dstb + (uint32_t)r * BROW + c, gp + (size_t)r * 512 + c);
}

__global__ __launch_bounds__(256, 2) void vq_mma_kernel(const float* __restrict__ x,
                                                        float* __restrict__ out,
                                                        long long loss_idx) {
    uint32_t sb = smem_u32(smem);
    int tid = threadIdx.x, lane = tid & 31, wid = tid >> 5;
    int wm = wid >> 2, wn = wid & 3;

    // B tiles 0,1 -> ring slots 0,1 (slots 2,3 are the phase-1 XS overlay)
    issueB_half(sb, tid, 0, 0); issueB_half(sb, tid, 0, 1); CP_COMMIT();
    issueB_half(sb, tid, 1, 0); issueB_half(sb, tid, 1, 1); CP_COMMIT();

    // ---- Phase 1: single-barrier pipelined A build + out copy + sum(x^2) ----
    int n0 = blockIdx.x * CTA_M;
    int b = n0 >> 10, hw0 = n0 & 1023;
    const float* xb = x + (size_t)b * (EDIM * 1024) + hw0;
    float* ob = out + (size_t)b * (EDIM * 1024) + hw0;
    float* xs = (float*)(smem + SM_XS);
    int row = tid & 127, h = tid >> 7;
    uint32_t sxp = (uint32_t)(row & 7) << 4;
    int c0 = tid >> 5, m0 = (tid & 31) * 4;          // stage slots (c0 0..7)
    int c1 = c0 + 8,   m1 = m0;                      // (c1 8..15)
    float sq = 0.f;
    float4 rv0 = *(const float4*)(xb + (size_t)c0 * 1024 + m0);
    float4 rv1 = *(const float4*)(xb + (size_t)c1 * 1024 + m1);
#pragma unroll 1
    for (int q = 0; q < 16; ++q) {                   // 16 dims per stage
        float* buf = xs + (q & 1) * 2048;
        *(float4*)(buf + c0 * 128 + m0) = rv0;
        *(float4*)(buf + c1 * 128 + m1) = rv1;
        *(float4*)(ob + (size_t)(q * 16 + c0) * 1024 + m0) = rv0;
        *(float4*)(ob + (size_t)(q * 16 + c1) * 1024 + m1) = rv1;
        sq += rv0.x * rv0.x + rv0.y * rv0.y + rv0.z * rv0.z + rv0.w * rv0.w;
        sq += rv1.x * rv1.x + rv1.y * rv1.y + rv1.z * rv1.z + rv1.w * rv1.w;
        if (q < 15) {                                // prefetch next stage
            rv0 = *(const float4*)(xb + (size_t)((q + 1) * 16 + c0) * 1024 + m0);
            rv1 = *(const float4*)(xb + (size_t)((q + 1) * 16 + c1) * 1024 + m1);
        }
        __syncthreads();                             // buf[q&1] complete
        float v[8];
#pragma unroll
        for (int m = 0; m < 8; ++m) v[m] = buf[(h * 8 + m) * 128 + row];
        uint4 w;
        w.x = pack_bf16x2(v[0], v[1]); w.y = pack_bf16x2(v[2], v[3]);
        w.z = pack_bf16x2(v[4], v[5]); w.w = pack_bf16x2(v[6], v[7]);
        uint32_t col = (uint32_t)(q * 32 + h * 16);
        *(uint4*)(smem + SM_A + row * 512 + (col ^ sxp)) = w;
    }
    __syncthreads();                                 // XS (slots 2,3) now dead
    // B tile 2 -> slot 2; EN load
    issueB_half(sb, tid, 2, 0); issueB_half(sb, tid, 2, 1); CP_COMMIT();
    {
        float4 e4 = ((const float4*)g_enorm2)[tid];
        *(float4*)(smem + SM_EN + tid * 16) = e4;
    }

    // ---- mainloop: ring-4, wait_group 2, issues interleaved with MMAs ----
    uint32_t sxl = (uint32_t)(lane & 7) << 4;
    uint32_t abase[4];
#pragma unroll
    for (int mi = 0; mi < 4; ++mi)
        abase[mi] = sb + SM_A + (uint32_t)(wm * 64 + mi * 16 + (lane & 15)) * 512;
    uint32_t colA_l = (uint32_t)(lane >> 4) * 16;
    uint32_t brow80 = (uint32_t)(wn * 32 + (lane & 7) + ((lane >> 4) & 1) * 8) * BROW;
    uint32_t colB_l = (uint32_t)((lane >> 3) & 1) * 16;

    float regmin[8];
#pragma unroll
    for (int i = 0; i < 8; ++i) regmin[i] = 3.0e38f;

#pragma unroll 1
    for (int nc = 0; nc < NCH; ++nc) {
        float acc[4][4][4];
#pragma unroll
        for (int mi = 0; mi < 4; ++mi)
#pragma unroll
            for (int nj = 0; nj < 4; ++nj)
#pragma unroll
                for (int c = 0; c < 4; ++c) acc[mi][nj][c] = 0.f;

#pragma unroll 1
        for (int kt = 0; kt < TPC; ++kt) {
            int t = nc * TPC + kt;
            CP_WAIT2();          // <=2 newer groups outstanding -> tile t ready
            __syncthreads();     // all warps done with tile t-4's slot
            uint32_t bufb = sb + SM_BR + (uint32_t)(t & 3) * BSLOT;
#pragma unroll
            for (int kq = 0; kq < 2; ++kq) {
                uint32_t cA = (uint32_t)((t & 7) * 64 + kq * 32) + colA_l;
                uint32_t cB = (uint32_t)(kq * 32) + colB_l;
                uint32_t bf[2][4];
                ldsm_x4t(bf[0], bufb + brow80 + cB);
                ldsm_x4t(bf[1], bufb + brow80 + 16 * BROW + cB);
                // interleave 1/2 of tile t+3's cp.asyncs into this kq slot
                if (t + 3 < NT) issueB_half(sb, tid, t + 3, kq);
#pragma unroll
                for (int mi = 0; mi < 4; ++mi) {
                    uint32_t af[4];
                    ldsm_x4(af, abase[mi] + (cA ^ sxl));
                    mma16816(acc[mi][0], af, &bf[0][0]);
                    mma16816(acc[mi][1], af, &bf[0][2]);
                    mma16816(acc[mi][2], af, &bf[1][0]);
                    mma16816(acc[mi][3], af, &bf[1][2]);
                }
            }
            CP_COMMIT();         // exactly one group per tile (may be empty)
        }
        // epilogue: fold en[k] - 2*dot into per-lane row minima
        const float* en = (const float*)(smem + SM_EN) + nc * 128;
#pragma unroll
        for (int nj = 0; nj < 4; ++nj) {
            int col = wn * 32 + nj * 8 + (lane & 3) * 2;
            float e0 = en[col], e1 = en[col + 1];
#pragma unroll
            for (int mi = 0; mi < 4; ++mi) {
                float s0 = fmaf(acc[mi][nj][0], -2.f, e0);
                float s1 = fmaf(acc[mi][nj][1], -2.f, e1);
                float s2 = fmaf(acc[mi][nj][2], -2.f, e0);
                float s3 = fmaf(acc[mi][nj][3], -2.f, e1);
                regmin[mi * 2 + 0] = fminf(regmin[mi * 2 + 0], fminf(s0, s1));
                regmin[mi * 2 + 1] = fminf(regmin[mi * 2 + 1], fminf(s2, s3));
            }
        }
    }

    // ---- reductions ----
#pragma unroll
    for (int i = 0; i < 8; ++i) {
        regmin[i] = fminf(regmin[i], __shfl_xor_sync(0xffffffffu, regmin[i], 1));
        regmin[i] = fminf(regmin[i], __shfl_xor_sync(0xffffffffu, regmin[i], 2));
    }
    float* rm = (float*)(smem + SM_RM);              // rm[wn][128]
    __syncthreads();
    if ((lane & 3) == 0) {
        int g = lane >> 2;
#pragma unroll
        for (int mi = 0; mi < 4; ++mi) {
            int r = wm * 64 + mi * 16 + g;
            rm[wn * 128 + r]     = regmin[mi * 2 + 0];
            rm[wn * 128 + r + 8] = regmin[mi * 2 + 1];
        }
    }
    __syncthreads();

    __shared__ float ws[16];
    float rsum = 0.f;
    if (tid < 128)
        rsum = fminf(fminf(rm[tid], rm[128 + tid]),
                     fminf(rm[256 + tid], rm[384 + tid]));
#pragma unroll
    for (int o = 16; o; o >>= 1) {
        rsum += __shfl_xor_sync(0xffffffffu, rsum, o);
        sq   += __shfl_xor_sync(0xffffffffu, sq, o);
    }
    if (lane == 0) { ws[wid] = rsum; ws[8 + wid] = sq; }
    __syncthreads();
    if (tid == 0) {
        atomicAdd(&g_summin, (double)(ws[0] + ws[1] + ws[2] + ws[3]));
        double t = 0.0;
#pragma unroll
        for (int i = 0; i < 8; ++i) t += (double)ws[8 + i];
        atomicAdd(&g_sumx2, t);
        __threadfence();
        unsigned done = atomicAdd(&g_count, 1u);
        if (done == gridDim.x - 1) {                 // last CTA computes the loss
            double sx = atomicAdd(&g_sumx2, 0.0);
            double sm = atomicAdd(&g_summin, 0.0);
            double mean = (sx + sm) / (double)((long long)NVEC * EDIM);
            out[loss_idx] = (float)(1.25 * mean);    // (1 + BETA) * mean
        }
    }
}

extern "C" void kernel_launch(void* const* d_in, const int* in_sizes, int n_in,
                              void* d_out, int out_size) {
    (void)n_in; (void)in_sizes;
    const float* x  = (const float*)d_in[0];
    const float* cb = (const float*)d_in[1];
    float* out = (float*)d_out;

    cudaFuncSetAttribute(vq_mma_kernel, cudaFuncAttributeMaxDynamicSharedMemorySize,
                         SMEM_TOTAL);

    prep_kernel<<<256, 256>>>(cb);
    vq_mma_kernel<<<NVEC / CTA_M, 256, SMEM_TOTAL>>>(x, out, (long long)out_size - 1);
}